// round 16
// baseline (speedup 1.0000x reference)
#include <cuda_runtime.h>
#include <cuda_fp16.h>
#include <cstdint>

// Problem constants
#define NUM_NODES 50000
#define NUM_EDGES 800000
#define D_IN  128
#define D_HID 128
#define D_OUT 40

#define SCAN_BLK 512
#define SCAN_NBLOCKS ((NUM_NODES + SCAN_BLK - 1) / SCAN_BLK)   // 98

// Scratch buffers (device globals; no allocation allowed)
// hw (projected messages) fp16: 128 half = 256 B = 16 uint4 per node.
__device__ uint4 g_bufHW16[NUM_NODES * 16];    // fp16 messages (layers 0/1)
__device__ float g_bufAGG[NUM_NODES * D_HID];  // fp32 aggregation
__device__ uint2 g_bufO16[NUM_NODES * 10];     // fp16 layer-2 projections (40 half)
__device__ int   g_is64;                       // edge_index dtype flag
__device__ int   g_deg[NUM_NODES];             // degree counts, then fill cursor
__device__ int   g_off[NUM_NODES + 1];         // CSR row offsets (by dst)
__device__ int   g_csrc[NUM_EDGES];            // CSR source ids
__device__ int   g_bsum[SCAN_NBLOCKS];         // per-block scan totals

// ---------------------------------------------------------------------------
// f32x2 packed-FMA helpers (Blackwell dual-FP32 pipe, PTX-only)
// ---------------------------------------------------------------------------
__device__ __forceinline__ unsigned long long pack2(float x, float y) {
    unsigned long long r;
    asm("mov.b64 %0, {%1, %2};" : "=l"(r) : "f"(x), "f"(y));
    return r;
}
__device__ __forceinline__ void unpack2(float& x, float& y, unsigned long long v) {
    asm("mov.b64 {%0, %1}, %2;" : "=f"(x), "=f"(y) : "l"(v));
}
#define FMA2(d, a, b) \
    asm("fma.rn.f32x2 %0, %1, %2, %0;" : "+l"(d) : "l"(a), "l"(b))

// accumulate 8 fp16 (uint4) into acc[0..7]
__device__ __forceinline__ void addh8(float* acc, uint4 u) {
    __half2* h = (__half2*)&u;
    #pragma unroll
    for (int j = 0; j < 4; j++) {
        float2 f = __half22float2(h[j]);
        acc[2 * j]     += f.x;
        acc[2 * j + 1] += f.y;
    }
}
// accumulate 4 fp16 (uint2) into acc[0..3]
__device__ __forceinline__ void addh4(float* acc, uint2 u) {
    __half2 a = *reinterpret_cast<__half2*>(&u.x);
    __half2 b = *reinterpret_cast<__half2*>(&u.y);
    float2 fa = __half22float2(a);
    float2 fb = __half22float2(b);
    acc[0] += fa.x; acc[1] += fa.y; acc[2] += fb.x; acc[3] += fb.y;
}

// ---------------------------------------------------------------------------
// zero degree counters + detect edge_index dtype (merged: 2 launches -> 1)
// ---------------------------------------------------------------------------
__global__ void zero_detect_kernel(const int* __restrict__ ei32) {
    int i = blockIdx.x * blockDim.x + threadIdx.x;
    if (i < NUM_NODES) g_deg[i] = 0;
    if (i == 0) {
        int is64 = 1;
        for (int k = 0; k < 256; k++) {
            if (ei32[2 * k + 1] != 0) { is64 = 0; break; }
        }
        g_is64 = is64;
    }
}

// ---------------------------------------------------------------------------
// CSR build: histogram(dst) -> scanA (block totals) -> scanC (apply) -> fill
// ---------------------------------------------------------------------------
__global__ void hist_kernel(const int* __restrict__ ei32, int E) {
    int e = blockIdx.x * blockDim.x + threadIdx.x;
    if (e >= E) return;
    int d = g_is64 ? ei32[2 * (E + e)] : ei32[E + e];
    atomicAdd(&g_deg[d], 1);
}

// Phase A: per-block exclusive scan (512 elems/block); write block TOTAL.
__global__ void scanA_kernel() {
    __shared__ int wsum[16];
    const int tid = threadIdx.x;
    const int lane = tid & 31, wid = tid >> 5;
    int i = blockIdx.x * SCAN_BLK + tid;
    int v = (i < NUM_NODES) ? g_deg[i] : 0;
    int x = v;
    #pragma unroll
    for (int s = 1; s < 32; s <<= 1) {
        int t = __shfl_up_sync(0xffffffffu, x, s);
        if (lane >= s) x += t;
    }
    if (lane == 31) wsum[wid] = x;
    __syncthreads();
    if (wid == 0 && lane < 16) {
        int y = wsum[lane];
        #pragma unroll
        for (int s = 1; s < 16; s <<= 1) {
            int t = __shfl_up_sync(0xffffu, y, s);
            if (lane >= s) y += t;
        }
        wsum[lane] = y;
    }
    __syncthreads();
    int warpoff = (wid == 0) ? 0 : wsum[wid - 1];
    if (i < NUM_NODES) g_off[i] = warpoff + x - v;   // exclusive within block
    if (tid == SCAN_BLK - 1) g_bsum[blockIdx.x] = wsum[15];
}

// Phase C (scanB merged in): each 256-thread block lies inside ONE scanA
// block (256 | 512); thread 0 prefixes the <=98 block totals serially.
__global__ void scanC_kernel() {
    __shared__ int base_s;
    int i = blockIdx.x * blockDim.x + threadIdx.x;
    if (threadIdx.x == 0) {
        int j = (blockIdx.x * 256) / SCAN_BLK;   // owning scanA block
        int base = 0;
        for (int k = 0; k < j; k++) base += g_bsum[k];
        base_s = base;
        if (blockIdx.x == 0) {
            int tot = base;  // j==0 -> 0
            for (int k = 0; k < SCAN_NBLOCKS; k++) tot += g_bsum[k];
            g_off[NUM_NODES] = tot;              // grand total (=E)
        }
    }
    __syncthreads();
    if (i >= NUM_NODES) return;
    int o = g_off[i] + base_s;
    g_off[i] = o;
    g_deg[i] = o;   // fill cursor
}

__global__ void fill_kernel(const int* __restrict__ ei32, int E) {
    int e = blockIdx.x * blockDim.x + threadIdx.x;
    if (e >= E) return;
    int s, d;
    if (g_is64) { s = ei32[2 * e]; d = ei32[2 * (E + e)]; }
    else        { s = ei32[e];     d = ei32[E + e]; }
    int pos = atomicAdd(&g_deg[d], 1);
    g_csrc[pos] = s;
}

// ---------------------------------------------------------------------------
// GEMM: C16[N,128](fp16) = act(A[N,128]) @ W[128,128]  — f32x2 packed FMA
// ---------------------------------------------------------------------------
template <bool RELU>
__global__ void gemm128_kernel(const float* __restrict__ A, const float* __restrict__ W,
                               __half* __restrict__ C16, int N) {
    extern __shared__ float sm[];
    float* Ws = sm;              // 128*128
    float* As = sm + 128 * 128;  // 64*128

    const int tid = threadIdx.x;

    {
        const float4* W4 = (const float4*)W;
        float4* Ws4 = (float4*)Ws;
        #pragma unroll
        for (int i = 0; i < 16; i++) Ws4[tid + i * 256] = W4[tid + i * 256];
    }
    const int rowBase = blockIdx.x * 64;
    {
        const float4* A4 = (const float4*)A;
        float4* As4 = (float4*)As;
        #pragma unroll
        for (int i = 0; i < 8; i++) {
            int idx = tid + i * 256;
            int r = idx >> 5;
            int c4 = idx & 31;
            float4 v = make_float4(0.f, 0.f, 0.f, 0.f);
            if (rowBase + r < N) {
                v = A4[(size_t)(rowBase + r) * 32 + c4];
                if (RELU) {
                    v.x = fmaxf(v.x, 0.f); v.y = fmaxf(v.y, 0.f);
                    v.z = fmaxf(v.z, 0.f); v.w = fmaxf(v.w, 0.f);
                }
            }
            As4[idx] = v;
        }
    }
    __syncthreads();

    const int lane = tid & 31;
    const int warp = tid >> 5;

    unsigned long long acc2[8][2];
    #pragma unroll
    for (int r = 0; r < 8; r++) { acc2[r][0] = 0ull; acc2[r][1] = 0ull; }

    for (int k = 0; k < 128; k += 4) {
        float4 a[8];
        #pragma unroll
        for (int r = 0; r < 8; r++)
            a[r] = *(const float4*)(As + (warp * 8 + r) * 128 + k);

        unsigned long long wlo[4], whi[4];
        #pragma unroll
        for (int kk = 0; kk < 4; kk++) {
            const unsigned long long* wp =
                (const unsigned long long*)(Ws + (k + kk) * 128 + lane * 4);
            wlo[kk] = wp[0];
            whi[kk] = wp[1];
        }

        #pragma unroll
        for (int kk = 0; kk < 4; kk++) {
            #pragma unroll
            for (int r = 0; r < 8; r++) {
                float av = (kk == 0) ? a[r].x : (kk == 1) ? a[r].y
                         : (kk == 2) ? a[r].z : a[r].w;
                unsigned long long av2 = pack2(av, av);
                FMA2(acc2[r][0], av2, wlo[kk]);
                FMA2(acc2[r][1], av2, whi[kk]);
            }
        }
    }

    #pragma unroll
    for (int r = 0; r < 8; r++) {
        int row = rowBase + warp * 8 + r;
        if (row < N) {
            float4 o;
            unpack2(o.x, o.y, acc2[r][0]);
            unpack2(o.z, o.w, acc2[r][1]);
            __half2 h01 = __floats2half2_rn(o.x, o.y);
            __half2 h23 = __floats2half2_rn(o.z, o.w);
            uint2 pv;
            pv.x = *reinterpret_cast<uint32_t*>(&h01);
            pv.y = *reinterpret_cast<uint32_t*>(&h23);
            *(uint2*)(C16 + (size_t)row * 128 + lane * 4) = pv;
        }
    }
}

// ---------------------------------------------------------------------------
// GEMM: C16[N,40](fp16) = relu(A[N,128]) @ W[128,40] — f32x2, one row/thread.
// ---------------------------------------------------------------------------
__global__ void gemm40_kernel(const float* __restrict__ A, const float* __restrict__ W,
                              __half* __restrict__ C16, int N) {
    __shared__ float Ws[128 * 40];
    for (int i = threadIdx.x; i < 128 * 40; i += blockDim.x) Ws[i] = W[i];
    __syncthreads();

    int row = blockIdx.x * blockDim.x + threadIdx.x;
    if (row >= N) return;

    unsigned long long acc2[20];
    #pragma unroll
    for (int j = 0; j < 20; j++) acc2[j] = 0ull;

    const float4* Arow = (const float4*)(A + (size_t)row * 128);
    for (int k4 = 0; k4 < 32; k4++) {
        float4 a = Arow[k4];
        a.x = fmaxf(a.x, 0.f); a.y = fmaxf(a.y, 0.f);
        a.z = fmaxf(a.z, 0.f); a.w = fmaxf(a.w, 0.f);
        #pragma unroll
        for (int kk = 0; kk < 4; kk++) {
            float av = (kk == 0) ? a.x : (kk == 1) ? a.y : (kk == 2) ? a.z : a.w;
            unsigned long long av2 = pack2(av, av);
            const unsigned long long* wrow =
                (const unsigned long long*)(Ws + (k4 * 4 + kk) * 40);
            #pragma unroll
            for (int j = 0; j < 20; j++) FMA2(acc2[j], av2, wrow[j]);
        }
    }

    uint32_t hv[20];
    #pragma unroll
    for (int j = 0; j < 20; j++) {
        float x, y;
        unpack2(x, y, acc2[j]);
        __half2 h = __floats2half2_rn(x, y);
        hv[j] = *reinterpret_cast<uint32_t*>(&h);
    }
    uint2* Co = (uint2*)(C16 + (size_t)row * 40);
    #pragma unroll
    for (int j = 0; j < 10; j++) Co[j] = make_uint2(hv[2 * j], hv[2 * j + 1]);
}

// ---------------------------------------------------------------------------
// CSR gather (128 dims, fp16): one warp per node; half-warps own alternate
// edges, lane loads uint4 (8 cols, 16B). Partner sums combined via shfl.
// ---------------------------------------------------------------------------
__global__ void gather128_kernel(const __half* __restrict__ hw16,
                                 const float* __restrict__ b,
                                 float* __restrict__ agg) {
    int w = (blockIdx.x * blockDim.x + threadIdx.x) >> 5;
    int lane = threadIdx.x & 31;
    if (w >= NUM_NODES) return;
    const int half = lane >> 4;    // which edge of a pair
    const int hl = lane & 15;      // owns cols hl*8 .. hl*8+7
    int beg = __ldg(&g_off[w]);
    int end = __ldg(&g_off[w + 1]);

    float acc[8];
    #pragma unroll
    for (int j = 0; j < 8; j++) acc[j] = 0.f;

    int i = beg;
    for (; i + 4 <= end; i += 4) {
        int sA = g_csrc[i + half];
        int sB = g_csrc[i + 2 + half];
        uint4 uA = *((const uint4*)(hw16 + (size_t)sA * 128) + hl);
        uint4 uB = *((const uint4*)(hw16 + (size_t)sB * 128) + hl);
        addh8(acc, uA);
        addh8(acc, uB);
    }
    for (; i + 2 <= end; i += 2) {
        int s = g_csrc[i + half];
        addh8(acc, *((const uint4*)(hw16 + (size_t)s * 128) + hl));
    }
    if (i < end && half == 0) {
        int s = g_csrc[i];
        addh8(acc, *((const uint4*)(hw16 + (size_t)s * 128) + hl));
    }

    // combine partner half-warp
    #pragma unroll
    for (int j = 0; j < 8; j++)
        acc[j] += __shfl_down_sync(0xffffffffu, acc[j], 16);

    if (half == 0) {
        float4 b0 = *(const float4*)(b + hl * 8);
        float4 b1 = *(const float4*)(b + hl * 8 + 4);
        float* dst = agg + (size_t)w * 128 + hl * 8;
        *(float4*)dst = make_float4(acc[0] + b0.x, acc[1] + b0.y,
                                    acc[2] + b0.z, acc[3] + b0.w);
        *(float4*)(dst + 4) = make_float4(acc[4] + b1.x, acc[5] + b1.y,
                                          acc[6] + b1.z, acc[7] + b1.w);
    }
}

// ---------------------------------------------------------------------------
// CSR gather (40 dims, fp16): one warp per node; half-warps own alternate
// edges, lanes hl<10 load uint2 (4 cols). Combine via shfl; fp32 out.
// ---------------------------------------------------------------------------
__global__ void gather40_kernel(const __half* __restrict__ hw16,
                                const float* __restrict__ b,
                                float* __restrict__ out) {
    int w = (blockIdx.x * blockDim.x + threadIdx.x) >> 5;
    int lane = threadIdx.x & 31;
    if (w >= NUM_NODES) return;
    const int half = lane >> 4;
    const int hl = lane & 15;      // active if hl<10; owns cols hl*4..+4
    int beg = __ldg(&g_off[w]);
    int end = __ldg(&g_off[w + 1]);

    float acc[4] = {0.f, 0.f, 0.f, 0.f};

    int i = beg;
    for (; i + 4 <= end; i += 4) {
        int sA = g_csrc[i + half];
        int sB = g_csrc[i + 2 + half];
        if (hl < 10) {
            addh4(acc, *((const uint2*)(hw16 + (size_t)sA * 40) + hl));
            addh4(acc, *((const uint2*)(hw16 + (size_t)sB * 40) + hl));
        }
    }
    for (; i + 2 <= end; i += 2) {
        int s = g_csrc[i + half];
        if (hl < 10) addh4(acc, *((const uint2*)(hw16 + (size_t)s * 40) + hl));
    }
    if (i < end && half == 0 && hl < 10) {
        int s = g_csrc[i];
        addh4(acc, *((const uint2*)(hw16 + (size_t)s * 40) + hl));
    }

    #pragma unroll
    for (int j = 0; j < 4; j++)
        acc[j] += __shfl_down_sync(0xffffffffu, acc[j], 16);

    if (half == 0 && hl < 10) {
        float4 bv = *(const float4*)(b + hl * 4);
        *(float4*)(out + (size_t)w * 40 + hl * 4) =
            make_float4(acc[0] + bv.x, acc[1] + bv.y, acc[2] + bv.z, acc[3] + bv.w);
    }
}

// ---------------------------------------------------------------------------
// Launch — minimized launch count: 5-kernel CSR chain on side stream
// (overlapped with layer-0 GEMM), then 5 main-stream kernels.
// ---------------------------------------------------------------------------
extern "C" void kernel_launch(void* const* d_in, const int* in_sizes, int n_in,
                              void* d_out, int out_size) {
    const float* x  = (const float*)d_in[0];
    const int*   ei = (const int*)d_in[1];
    const float* W0 = (const float*)d_in[2];
    const float* b0 = (const float*)d_in[3];
    const float* W1 = (const float*)d_in[4];
    const float* b1 = (const float*)d_in[5];
    const float* W2 = (const float*)d_in[6];
    const float* b2 = (const float*)d_in[7];
    float* out = (float*)d_out;

    const int N = NUM_NODES, E = NUM_EDGES;

    __half *bufHW16, *bufO16;
    float* bufAGG;
    cudaGetSymbolAddress((void**)&bufHW16, g_bufHW16);
    cudaGetSymbolAddress((void**)&bufAGG, g_bufAGG);
    cudaGetSymbolAddress((void**)&bufO16, g_bufO16);

    const int SMEM = (128 * 128 + 64 * 128) * sizeof(float);  // 96KB
    cudaFuncSetAttribute(gemm128_kernel<false>, cudaFuncAttributeMaxDynamicSharedMemorySize, SMEM);
    cudaFuncSetAttribute(gemm128_kernel<true>,  cudaFuncAttributeMaxDynamicSharedMemorySize, SMEM);

    static cudaStream_t s1 = nullptr;
    static cudaEvent_t evFork = nullptr, evCSR = nullptr;
    if (s1 == nullptr) {
        cudaStreamCreateWithFlags(&s1, cudaStreamNonBlocking);
        cudaEventCreateWithFlags(&evFork, cudaEventDisableTiming);
        cudaEventCreateWithFlags(&evCSR,  cudaEventDisableTiming);
    }

    // --- fork: CSR build on s1 (5 launches), layer-0 GEMM on main ---
    cudaEventRecord(evFork, 0);
    cudaStreamWaitEvent(s1, evFork, 0);

    zero_detect_kernel<<<(N + 255) / 256, 256, 0, s1>>>(ei);
    hist_kernel<<<(E + 255) / 256, 256, 0, s1>>>(ei, E);
    scanA_kernel<<<SCAN_NBLOCKS, SCAN_BLK, 0, s1>>>();
    scanC_kernel<<<(N + 255) / 256, 256, 0, s1>>>();
    fill_kernel<<<(E + 255) / 256, 256, 0, s1>>>(ei, E);
    cudaEventRecord(evCSR, s1);

    gemm128_kernel<false><<<(N + 63) / 64, 256, SMEM>>>(x, W0, bufHW16, N);

    // --- join CSR ---
    cudaStreamWaitEvent(0, evCSR, 0);

    const int GWARP_BLOCKS = (N * 32 + 255) / 256;  // 1 warp per node

    // Layer 0 aggregate
    gather128_kernel<<<GWARP_BLOCKS, 256>>>(bufHW16, b0, bufAGG);

    // Layer 1
    gemm128_kernel<true><<<(N + 63) / 64, 256, SMEM>>>(bufAGG, W1, bufHW16, N);
    gather128_kernel<<<GWARP_BLOCKS, 256>>>(bufHW16, b1, bufAGG);

    // Layer 2
    gemm40_kernel<<<(N + 255) / 256, 256>>>(bufAGG, W2, bufO16, N);
    gather40_kernel<<<GWARP_BLOCKS, 256>>>(bufO16, b2, out);
}